// round 1
// baseline (speedup 1.0000x reference)
#include <cuda_runtime.h>

#define N    8192
#define FIN  256
#define FOUT 128
#define RPB  64    // rows per block in attention kernel
#define JT   32    // j-tile

// scratch (device globals: no allocations allowed)
__device__ float g_Wh[N * FOUT];
__device__ float g_p[N], g_r[N], g_th[N];   // exp(s_src), exp(0.2 s_src), -s_src
__device__ float g_q[N], g_t[N], g_sd[N];   // exp(s_dst), exp(0.2 s_dst), s_dst

// ---- packed f32x2 helpers (sm_100+) ----
__device__ __forceinline__ void fma2(unsigned long long& d, unsigned long long a, unsigned long long b) {
    asm("fma.rn.f32x2 %0, %1, %2, %0;" : "+l"(d) : "l"(a), "l"(b));
}
__device__ __forceinline__ unsigned long long bcast2(float w) {
    unsigned long long d;
    asm("mov.b64 %0, {%1, %1};" : "=l"(d) : "f"(w));
    return d;
}

// =====================================================================
// Kernel 1: Wh = h @ W^T   (N x FIN) @ (FOUT x FIN)^T -> (N x FOUT)
// 128 CTAs x 256 thr; 64 rows per CTA; k-tiles of 64.
// =====================================================================
__global__ __launch_bounds__(256) void k_wh(const float* __restrict__ h,
                                            const float* __restrict__ W) {
    __shared__ float sh_h[64][68];          // [row][c]
    __shared__ float sh_w[64][FOUT + 4];    // [c][f] (transposed W tile)
    const int tid = threadIdx.x;
    const int i0  = blockIdx.x * 64;
    const int fg  = tid & 15;   // feature group: f = 8*fg .. 8*fg+7
    const int rg  = tid >> 4;   // row group:     r = 4*rg .. 4*rg+3

    float acc[4][8];
#pragma unroll
    for (int r = 0; r < 4; r++)
#pragma unroll
        for (int u = 0; u < 8; u++) acc[r][u] = 0.f;

    for (int kt = 0; kt < FIN / 64; kt++) {
        const int c0 = kt * 64;
        __syncthreads();
        // load h tile: 64 x 64
        {
            const int rr  = tid >> 2;
            const int cc0 = (tid & 3) * 16;
#pragma unroll
            for (int u = 0; u < 4; u++) {
                float4 v = *(const float4*)&h[(size_t)(i0 + rr) * FIN + c0 + cc0 + 4 * u];
                *(float4*)&sh_h[rr][cc0 + 4 * u] = v;
            }
        }
        // load W tile transposed: sh_w[c][f]
        {
            const int f   = tid >> 1;
            const int cc0 = (tid & 1) * 32;
#pragma unroll
            for (int u = 0; u < 8; u++) {
                float4 v = *(const float4*)&W[(size_t)f * FIN + c0 + cc0 + 4 * u];
                sh_w[cc0 + 4 * u + 0][f] = v.x;
                sh_w[cc0 + 4 * u + 1][f] = v.y;
                sh_w[cc0 + 4 * u + 2][f] = v.z;
                sh_w[cc0 + 4 * u + 3][f] = v.w;
            }
        }
        __syncthreads();
#pragma unroll 4
        for (int c = 0; c < 64; c++) {
            float hv[4];
#pragma unroll
            for (int r = 0; r < 4; r++) hv[r] = sh_h[rg * 4 + r][c];
            float4 wa = *(const float4*)&sh_w[c][fg * 8];
            float4 wb = *(const float4*)&sh_w[c][fg * 8 + 4];
#pragma unroll
            for (int r = 0; r < 4; r++) {
                acc[r][0] += hv[r] * wa.x;  acc[r][1] += hv[r] * wa.y;
                acc[r][2] += hv[r] * wa.z;  acc[r][3] += hv[r] * wa.w;
                acc[r][4] += hv[r] * wb.x;  acc[r][5] += hv[r] * wb.y;
                acc[r][6] += hv[r] * wb.z;  acc[r][7] += hv[r] * wb.w;
            }
        }
    }
#pragma unroll
    for (int r = 0; r < 4; r++) {
        const int row = i0 + rg * 4 + r;
        float4 oa = {acc[r][0], acc[r][1], acc[r][2], acc[r][3]};
        float4 ob = {acc[r][4], acc[r][5], acc[r][6], acc[r][7]};
        *(float4*)&g_Wh[(size_t)row * FOUT + fg * 8]     = oa;
        *(float4*)&g_Wh[(size_t)row * FOUT + fg * 8 + 4] = ob;
    }
}

// =====================================================================
// Kernel 2: s_src/s_dst per row + exp decomposition terms.
// One warp per row; 1024 CTAs x 256 thr.
// =====================================================================
__global__ __launch_bounds__(256) void k_s(const float* __restrict__ a) {
    const int row  = blockIdx.x * 8 + (threadIdx.x >> 5);
    const int lane = threadIdx.x & 31;
    float ssrc = 0.f, sdst = 0.f;
#pragma unroll
    for (int u = 0; u < 4; u++) {
        const int f = lane + u * 32;
        float v = g_Wh[(size_t)row * FOUT + f];
        ssrc += v * a[f];
        sdst += v * a[FOUT + f];
    }
#pragma unroll
    for (int o = 16; o; o >>= 1) {
        ssrc += __shfl_xor_sync(0xffffffffu, ssrc, o);
        sdst += __shfl_xor_sync(0xffffffffu, sdst, o);
    }
    if (lane == 0) {
        g_p[row]  = expf(ssrc);
        g_r[row]  = expf(0.2f * ssrc);
        g_th[row] = -ssrc;
        g_q[row]  = expf(sdst);
        g_t[row]  = expf(0.2f * sdst);
        g_sd[row] = sdst;
    }
}

// =====================================================================
// Kernel 3: out[i] = (sum_j w_ij * Wh[j]) / (sum_j w_ij)
//   w_ij = adj_ij ? ((s_src_i + s_dst_j > 0) ? p_i q_j : r_i t_j) : 0
// 128 CTAs x 256 thr; 64 rows/CTA; j-tiles of 32, adj+Wh prefetched
// into registers one tile ahead (latency hidden under the FMA phase).
// =====================================================================
__global__ __launch_bounds__(256) void k_att(const int* __restrict__ adj,
                                             float* __restrict__ out) {
    __shared__ float wh_sh[JT * FOUT];     // [j][f]
    __shared__ float w_sh[RPB * JT];       // [r][j]
    __shared__ float p_sh[RPB], r_sh[RPB], th_sh[RPB];
    __shared__ float dinv_sh[RPB];

    const int tid  = threadIdx.x;
    const int lane = tid & 31;
    const int wid  = tid >> 5;
    const int i0   = blockIdx.x * RPB;

    if (tid < RPB) {
        p_sh[tid]  = g_p[i0 + tid];
        r_sh[tid]  = g_r[i0 + tid];
        th_sh[tid] = g_th[i0 + tid];
    }

    unsigned long long acc2[16];
#pragma unroll
    for (int u = 0; u < 16; u++) acc2[u] = 0ull;
    float dacc[8];
#pragma unroll
    for (int k = 0; k < 8; k++) dacc[k] = 0.f;

    // prefetch registers
    int   aj[8];
    float qv, tv, sdv;
    float4 whv[4];

    // prefetch tile 0
    {
        const int j0 = 0;
        qv = g_q[j0 + lane];  tv = g_t[j0 + lane];  sdv = g_sd[j0 + lane];
#pragma unroll
        for (int k = 0; k < 8; k++)
            aj[k] = adj[(size_t)(i0 + wid + 8 * k) * N + j0 + lane];
        const float4* src = (const float4*)(g_Wh + (size_t)j0 * FOUT);
#pragma unroll
        for (int u = 0; u < 4; u++) whv[u] = src[tid + 256 * u];
    }
    __syncthreads();

    const int NT = N / JT;
    for (int t = 0; t < NT; t++) {
        // ---- stage phase: compute weights, fill smem ----
#pragma unroll
        for (int k = 0; k < 8; k++) {
            const int r = wid + 8 * k;
            float w = 0.f;
            if (aj[k] > 0)
                w = (sdv > th_sh[r]) ? p_sh[r] * qv : r_sh[r] * tv;
            w_sh[r * JT + lane] = w;
            dacc[k] += w;
        }
        {
            float4* dst = (float4*)wh_sh;
#pragma unroll
            for (int u = 0; u < 4; u++) dst[tid + 256 * u] = whv[u];
        }
        // ---- issue prefetch for next tile (hidden under FMA phase) ----
        {
            const int jn = (t + 1 < NT) ? (t + 1) * JT : 0;
            qv = g_q[jn + lane];  tv = g_t[jn + lane];  sdv = g_sd[jn + lane];
#pragma unroll
            for (int k = 0; k < 8; k++)
                aj[k] = adj[(size_t)(i0 + wid + 8 * k) * N + jn + lane];
            const float4* src = (const float4*)(g_Wh + (size_t)jn * FOUT);
#pragma unroll
            for (int u = 0; u < 4; u++) whv[u] = src[tid + 256 * u];
        }
        __syncthreads();
        // ---- FMA phase: this thread owns rows wid*8..wid*8+7, feats 4*lane..4*lane+3 ----
#pragma unroll 2
        for (int j = 0; j < JT; j += 4) {
            ulonglong2 bv[4];
#pragma unroll
            for (int u = 0; u < 4; u++)
                bv[u] = *(const ulonglong2*)&wh_sh[(j + u) * FOUT + lane * 4];
#pragma unroll
            for (int r = 0; r < 8; r++) {
                const float4 w4 = *(const float4*)&w_sh[(wid * 8 + r) * JT + j];
                unsigned long long ww;
                ww = bcast2(w4.x); fma2(acc2[2*r], ww, bv[0].x); fma2(acc2[2*r+1], ww, bv[0].y);
                ww = bcast2(w4.y); fma2(acc2[2*r], ww, bv[1].x); fma2(acc2[2*r+1], ww, bv[1].y);
                ww = bcast2(w4.z); fma2(acc2[2*r], ww, bv[2].x); fma2(acc2[2*r+1], ww, bv[2].y);
                ww = bcast2(w4.w); fma2(acc2[2*r], ww, bv[3].x); fma2(acc2[2*r+1], ww, bv[3].y);
            }
        }
        __syncthreads();   // everyone done reading smem before next stage overwrites
    }

    // denominator reduce: lane-partials -> full row sums
#pragma unroll
    for (int k = 0; k < 8; k++) {
        float d = dacc[k];
#pragma unroll
        for (int o = 16; o; o >>= 1) d += __shfl_xor_sync(0xffffffffu, d, o);
        if (lane == 0) dinv_sh[wid + 8 * k] = 1.0f / d;
    }
    __syncthreads();

#pragma unroll
    for (int r = 0; r < 8; r++) {
        const int row = wid * 8 + r;
        const float inv = dinv_sh[row];
        float2 lo, hi;
        lo = *(float2*)&acc2[2 * r];
        hi = *(float2*)&acc2[2 * r + 1];
        float4 o = {lo.x * inv, lo.y * inv, hi.x * inv, hi.y * inv};
        *(float4*)&out[(size_t)(i0 + row) * FOUT + lane * 4] = o;
    }
}

extern "C" void kernel_launch(void* const* d_in, const int* in_sizes, int n_in,
                              void* d_out, int out_size) {
    const float* h   = (const float*)d_in[0];
    const int*   adj = (const int*)d_in[1];
    const float* W   = (const float*)d_in[2];
    const float* a   = (const float*)d_in[3];
    float* out = (float*)d_out;

    k_wh<<<N / 64, 256>>>(h, W);
    k_s<<<N / 8, 256>>>(a);
    k_att<<<N / RPB, 256>>>(adj, out);
}

// round 8
// speedup vs baseline: 2.0576x; 2.0576x over previous
#include <cuda_runtime.h>
#include <cuda_bf16.h>
#include <cstdint>

#define N    8192
#define FIN  256
#define FOUT 128
#define KC   64          // K-chunk (j) per stage
#define KSPLIT 2         // split-K factor
#define KHALF (N / KSPLIT)
#define NT   (KHALF / KC)
#define STRD 68          // f32 row stride in smem tiles (68 % 32 == 4 -> ldmatrix conflict-free)

// ---------------- scratch (device globals; no allocs allowed) ----------------
__device__ float g_Wh[N * FOUT];                  // fp32 Wh (for k_s)
__device__ float g_WhT[FOUT * N];                 // tf32-rounded Wh transposed [f][j] (MMA B)
__device__ float g_p[N], g_r[N], g_th[N];         // exp(s_src), exp(0.2 s_src), -s_src
__device__ float g_q[N], g_t[N], g_sd[N];         // exp(s_dst), exp(0.2 s_dst), s_dst
__device__ float g_pD[128 * 128 * 128];           // partial numerators [cta][row][col]
__device__ float g_pden[128 * 128];               // partial denominators [cta][row]

// ---------------- helpers ----------------
__device__ __forceinline__ uint32_t smem_u32(const void* p) {
    uint32_t a;
    asm("{ .reg .u64 t; cvta.to.shared.u64 t, %1; cvt.u32.u64 %0, t; }" : "=r"(a) : "l"(p));
    return a;
}
__device__ __forceinline__ uint32_t f2tf32(float f) {
    uint32_t r;
    asm("cvt.rna.tf32.f32 %0, %1;" : "=r"(r) : "f"(f));
    return r;
}
__device__ __forceinline__ void ldsm4(uint32_t* r, uint32_t addr) {
    asm volatile("ldmatrix.sync.aligned.m8n8.x4.shared.b16 {%0,%1,%2,%3}, [%4];"
        : "=r"(r[0]), "=r"(r[1]), "=r"(r[2]), "=r"(r[3]) : "r"(addr));
}
__device__ __forceinline__ void mma_tf32(float* d, const uint32_t* a, const uint32_t* b) {
    asm volatile("mma.sync.aligned.m16n8k8.row.col.f32.tf32.tf32.f32 "
        "{%0,%1,%2,%3}, {%4,%5,%6,%7}, {%8,%9}, {%0,%1,%2,%3};"
        : "+f"(d[0]), "+f"(d[1]), "+f"(d[2]), "+f"(d[3])
        : "r"(a[0]), "r"(a[1]), "r"(a[2]), "r"(a[3]), "r"(b[0]), "r"(b[1]));
}

// =====================================================================
// Kernel 1: Wh = h @ W^T ; also emits g_WhT (tf32-rounded fp32, [f][j])
// =====================================================================
__global__ __launch_bounds__(256) void k_wh(const float* __restrict__ h,
                                            const float* __restrict__ W) {
    __shared__ __align__(16) float sh_h[64][68];
    __shared__ __align__(16) float sh_w[64][FOUT + 4];
    const int tid = threadIdx.x;
    const int i0  = blockIdx.x * 64;
    const int fg  = tid & 15;
    const int rg  = tid >> 4;

    float acc[4][8];
#pragma unroll
    for (int r = 0; r < 4; r++)
#pragma unroll
        for (int u = 0; u < 8; u++) acc[r][u] = 0.f;

    for (int kt = 0; kt < FIN / 64; kt++) {
        const int c0 = kt * 64;
        __syncthreads();
        {
            const int rr = tid >> 2, cc0 = (tid & 3) * 16;
#pragma unroll
            for (int u = 0; u < 4; u++)
                *(float4*)&sh_h[rr][cc0 + 4 * u] =
                    *(const float4*)&h[(size_t)(i0 + rr) * FIN + c0 + cc0 + 4 * u];
        }
        {
            const int f = tid >> 1, cc0 = (tid & 1) * 32;
#pragma unroll
            for (int u = 0; u < 8; u++) {
                float4 v = *(const float4*)&W[(size_t)f * FIN + c0 + cc0 + 4 * u];
                sh_w[cc0 + 4 * u + 0][f] = v.x;
                sh_w[cc0 + 4 * u + 1][f] = v.y;
                sh_w[cc0 + 4 * u + 2][f] = v.z;
                sh_w[cc0 + 4 * u + 3][f] = v.w;
            }
        }
        __syncthreads();
#pragma unroll 4
        for (int c = 0; c < 64; c++) {
            float hv[4];
#pragma unroll
            for (int r = 0; r < 4; r++) hv[r] = sh_h[rg * 4 + r][c];
            float4 wa = *(const float4*)&sh_w[c][fg * 8];
            float4 wb = *(const float4*)&sh_w[c][fg * 8 + 4];
#pragma unroll
            for (int r = 0; r < 4; r++) {
                acc[r][0] += hv[r] * wa.x;  acc[r][1] += hv[r] * wa.y;
                acc[r][2] += hv[r] * wa.z;  acc[r][3] += hv[r] * wa.w;
                acc[r][4] += hv[r] * wb.x;  acc[r][5] += hv[r] * wb.y;
                acc[r][6] += hv[r] * wb.z;  acc[r][7] += hv[r] * wb.w;
            }
        }
    }
#pragma unroll
    for (int r = 0; r < 4; r++) {
        const int row = i0 + rg * 4 + r;
        float4 oa = {acc[r][0], acc[r][1], acc[r][2], acc[r][3]};
        float4 ob = {acc[r][4], acc[r][5], acc[r][6], acc[r][7]};
        *(float4*)&g_Wh[(size_t)row * FOUT + fg * 8]     = oa;
        *(float4*)&g_Wh[(size_t)row * FOUT + fg * 8 + 4] = ob;
    }
    // ---- g_WhT: tf32-rounded, scattered stores (transposed [f][j]) ----
#pragma unroll
    for (int r = 0; r < 4; r++)
#pragma unroll
        for (int u = 0; u < 8; u++)
            g_WhT[(size_t)(fg * 8 + u) * N + i0 + rg * 4 + r] =
                __uint_as_float(f2tf32(acc[r][u]));
}

// =====================================================================
// Kernel 2: per-row attention scalars
// =====================================================================
__global__ __launch_bounds__(256) void k_s(const float* __restrict__ a) {
    const int row  = blockIdx.x * 8 + (threadIdx.x >> 5);
    const int lane = threadIdx.x & 31;
    float ssrc = 0.f, sdst = 0.f;
#pragma unroll
    for (int u = 0; u < 4; u++) {
        const int f = lane + u * 32;
        float v = g_Wh[(size_t)row * FOUT + f];
        ssrc += v * a[f];
        sdst += v * a[FOUT + f];
    }
#pragma unroll
    for (int o = 16; o; o >>= 1) {
        ssrc += __shfl_xor_sync(0xffffffffu, ssrc, o);
        sdst += __shfl_xor_sync(0xffffffffu, sdst, o);
    }
    if (lane == 0) {
        g_p[row]  = expf(ssrc);
        g_r[row]  = expf(0.2f * ssrc);
        g_th[row] = -ssrc;
        g_q[row]  = expf(sdst);
        g_t[row]  = expf(0.2f * sdst);
        g_sd[row] = sdst;
    }
}

// =====================================================================
// Kernel 3: attention GEMM via mma.sync tf32, split-K x2.
// grid 128: bx>>1 = M-tile (128 rows), bx&1 = K half. 256 threads.
// Dynamic smem: Bsh [128f][STRD], Ash [128row][STRD], p/r/th.
// =====================================================================
#define SM_B   0
#define SM_A   (128 * STRD * 4)
#define SM_P   (2 * 128 * STRD * 4)
#define SM_R   (SM_P + 512)
#define SM_TH  (SM_R + 512)
#define SM_TOT (SM_TH + 512)

__global__ __launch_bounds__(256) void k_att(const int* __restrict__ adj) {
    extern __shared__ __align__(16) char sm[];
    const uint32_t smb = smem_u32(sm);
    float* Bsh  = (float*)(sm + SM_B);
    float* Ash  = (float*)(sm + SM_A);
    float* psh  = (float*)(sm + SM_P);
    float* rsh  = (float*)(sm + SM_R);
    float* thsh = (float*)(sm + SM_TH);

    const int tid  = threadIdx.x;
    const int lane = tid & 31;
    const int wid  = tid >> 5;
    const int bx   = blockIdx.x;
    const int i0   = (bx >> 1) * 128;
    const int jb   = (bx & 1) * KHALF;

    if (tid < 128) {
        psh[tid]  = g_p[i0 + tid];
        rsh[tid]  = g_r[i0 + tid];
        thsh[tid] = g_th[i0 + tid];
    }

    // warp tiling: mw = m-block (32 rows), nw = n-block (64 cols)
    const int mw = wid & 3, nw = wid >> 2;
    // ldmatrix lane addressing (32-bit crosswise f32 tiles)
    const int arow = (lane & 7) + ((lane >> 3) & 1) * 8;  // A: tiles {m0-7,k0-3},{m8-15,k0-3},{m0-7,k4-7},{m8-15,k4-7}
    const int akseg = (lane >> 4) * 4;
    const int brow = (lane & 7) + ((lane >> 4) & 1) * 8;  // B: tiles {n0-7,k0-3},{n0-7,k4-7},{n8-15,k0-3},{n8-15,k4-7}
    const int bkseg = ((lane >> 3) & 1) * 4;
    const uint32_t aAddr0 = smb + SM_A + (uint32_t)((mw * 32 + arow) * STRD + akseg) * 4;
    const uint32_t bAddr0 = smb + SM_B + (uint32_t)((nw * 64 + brow) * STRD + bkseg) * 4;

    float acc[2][8][4];
#pragma unroll
    for (int mt = 0; mt < 2; mt++)
#pragma unroll
        for (int nt = 0; nt < 8; nt++)
#pragma unroll
            for (int u = 0; u < 4; u++) acc[mt][nt][u] = 0.f;
    float dacc[16];
#pragma unroll
    for (int u = 0; u < 16; u++) dacc[u] = 0.f;

    const int bf = tid >> 1, bseg = tid & 1;   // B-load: row f, 32-j segment

    // ---- prefetch chunk 0 ----
    int2   aj[16];
    float2 q2, t2, s2;
    float4 breg[8];
    {
        const int j0 = jb;
        q2 = *(const float2*)&g_q[j0 + 2 * lane];
        t2 = *(const float2*)&g_t[j0 + 2 * lane];
        s2 = *(const float2*)&g_sd[j0 + 2 * lane];
#pragma unroll
        for (int rr = 0; rr < 16; rr++)
            aj[rr] = *(const int2*)&adj[(size_t)(i0 + wid * 16 + rr) * N + j0 + 2 * lane];
        const float4* src = (const float4*)(g_WhT + (size_t)bf * N + j0 + bseg * 32);
#pragma unroll
        for (int u = 0; u < 8; u++) breg[u] = src[u];
    }
    __syncthreads();

    for (int t = 0; t < NT; t++) {
        // ---- stage: B regs -> smem (fp32, already tf32-rounded) ----
        {
            float4* dst = (float4*)(Bsh + bf * STRD + bseg * 32);
#pragma unroll
            for (int u = 0; u < 8; u++) dst[u] = breg[u];
        }
        // ---- stage: weights -> Ash (tf32-rounded), denominator accumulate ----
#pragma unroll
        for (int rr = 0; rr < 16; rr++) {
            const int row = wid * 16 + rr;
            const float pv = psh[row], rv = rsh[row], th = thsh[row];
            float w0 = 0.f, w1 = 0.f;
            if (aj[rr].x > 0) w0 = (s2.x > th) ? pv * q2.x : rv * t2.x;
            if (aj[rr].y > 0) w1 = (s2.y > th) ? pv * q2.y : rv * t2.y;
            const uint32_t u0 = f2tf32(w0), u1 = f2tf32(w1);
            uint2 wpk = {u0, u1};
            *(uint2*)(Ash + row * STRD + 2 * lane) = wpk;
            dacc[rr] += __uint_as_float(u0) + __uint_as_float(u1);
        }
        // ---- prefetch next chunk (hidden under mma phase) ----
        {
            const int jn = (t + 1 < NT) ? jb + (t + 1) * KC : jb;
            q2 = *(const float2*)&g_q[jn + 2 * lane];
            t2 = *(const float2*)&g_t[jn + 2 * lane];
            s2 = *(const float2*)&g_sd[jn + 2 * lane];
#pragma unroll
            for (int rr = 0; rr < 16; rr++)
                aj[rr] = *(const int2*)&adj[(size_t)(i0 + wid * 16 + rr) * N + jn + 2 * lane];
            const float4* src = (const float4*)(g_WhT + (size_t)bf * N + jn + bseg * 32);
#pragma unroll
            for (int u = 0; u < 8; u++) breg[u] = src[u];
        }
        __syncthreads();
        // ---- mma phase: 8 k-steps of 8 (tf32) ----
#pragma unroll
        for (int ks = 0; ks < 8; ks++) {
            uint32_t af[2][4];
            ldsm4(af[0], aAddr0 + (ks * 8) * 4);
            ldsm4(af[1], aAddr0 + (16 * STRD + ks * 8) * 4);
#pragma unroll
            for (int np = 0; np < 4; np++) {
                uint32_t bfr[4];
                ldsm4(bfr, bAddr0 + (np * 16 * STRD + ks * 8) * 4);
                mma_tf32(acc[0][2 * np],     af[0], bfr);
                mma_tf32(acc[0][2 * np + 1], af[0], bfr + 2);
                mma_tf32(acc[1][2 * np],     af[1], bfr);
                mma_tf32(acc[1][2 * np + 1], af[1], bfr + 2);
            }
        }
        __syncthreads();
    }

    // ---- denominator partials ----
#pragma unroll
    for (int rr = 0; rr < 16; rr++) {
        float d = dacc[rr];
#pragma unroll
        for (int o = 16; o; o >>= 1) d += __shfl_xor_sync(0xffffffffu, d, o);
        if (lane == 0) g_pden[bx * 128 + wid * 16 + rr] = d;
    }

    // ---- epilogue: accumulators -> g_pD[bx][row][col] ----
    {
        const int gid = lane >> 2, tig = lane & 3;
        float* base = g_pD + (size_t)bx * 16384;
#pragma unroll
        for (int mt = 0; mt < 2; mt++) {
            const int row = mw * 32 + mt * 16 + gid;
#pragma unroll
            for (int nt = 0; nt < 8; nt++) {
                const int col = nw * 64 + nt * 8 + 2 * tig;
                float2 lo = {acc[mt][nt][0], acc[mt][nt][1]};
                float2 hi = {acc[mt][nt][2], acc[mt][nt][3]};
                *(float2*)(base + (size_t)row * 128 + col)       = lo;
                *(float2*)(base + (size_t)(row + 8) * 128 + col) = hi;
            }
        }
    }
}

// =====================================================================
// Kernel 4: combine split-K partials, normalize
// =====================================================================
__global__ __launch_bounds__(256) void k_red(float* __restrict__ out) {
    __shared__ float dinv[128];
    const int mt = blockIdx.x, tid = threadIdx.x;
    if (tid < 128)
        dinv[tid] = 1.0f / (g_pden[(2 * mt) * 128 + tid] + g_pden[(2 * mt + 1) * 128 + tid]);
    __syncthreads();
    const float4* p0 = (const float4*)(g_pD + (size_t)(2 * mt) * 16384);
    const float4* p1 = (const float4*)(g_pD + (size_t)(2 * mt + 1) * 16384);
    float4* o = (float4*)(out + (size_t)mt * 16384);
#pragma unroll
    for (int u = 0; u < 16; u++) {
        const int idx = tid + 256 * u;           // float4 index (4096 total)
        float4 a = p0[idx], b = p1[idx];
        const float inv = dinv[idx >> 5];        // row = (idx*4)>>7
        float4 r = {(a.x + b.x) * inv, (a.y + b.y) * inv,
                    (a.z + b.z) * inv, (a.w + b.w) * inv};
        o[idx] = r;
    }
}

extern "C" void kernel_launch(void* const* d_in, const int* in_sizes, int n_in,
                              void* d_out, int out_size) {
    const float* h   = (const float*)d_in[0];
    const int*   adj = (const int*)d_in[1];
    const float* W   = (const float*)d_in[2];
    const float* a   = (const float*)d_in[3];
    float* out = (float*)d_out;

    cudaFuncSetAttribute(k_att, cudaFuncAttributeMaxDynamicSharedMemorySize, SM_TOT);

    k_wh<<<N / 64, 256>>>(h, W);
    k_s<<<N / 8, 256>>>(a);
    k_att<<<64 * KSPLIT, 256, SM_TOT>>>(adj);
    k_red<<<64, 256>>>(out);
}

// round 12
// speedup vs baseline: 3.1922x; 1.5514x over previous
#include <cuda_runtime.h>
#include <cuda_fp16.h>
#include <cstdint>

#define N    8192
#define FIN  256
#define FOUT 128
#define KC   64          // K-chunk (j) per stage
#define KSPLIT 2         // split-K factor
#define KHALF (N / KSPLIT)
#define NT   (KHALF / KC)

// ---------------- scratch (device globals; no allocs allowed) ----------------
__device__ float g_Wh[N * FOUT];                  // fp32 Wh (for k_s)
__device__ __half g_WhT[FOUT * N];                // fp16 Wh transposed [f][j] (MMA B)
__device__ float g_p[N], g_r[N], g_th[N];         // exp(s_src), exp(0.2 s_src), -s_src
__device__ float g_q[N], g_t[N], g_sd[N];         // exp(s_dst), exp(0.2 s_dst), s_dst
__device__ float g_pD[128 * 128 * 128];           // partial numerators [cta][row][col]
__device__ float g_pden[128 * 128];               // partial denominators [cta][row]

// ---------------- helpers ----------------
__device__ __forceinline__ uint32_t smem_u32(const void* p) {
    uint32_t a;
    asm("{ .reg .u64 t; cvta.to.shared.u64 t, %1; cvt.u32.u64 %0, t; }" : "=r"(a) : "l"(p));
    return a;
}
__device__ __forceinline__ uint32_t pack_f16x2(float lo, float hi) {
    uint32_t r;
    asm("cvt.rn.satfinite.f16x2.f32 %0, %1, %2;" : "=r"(r) : "f"(hi), "f"(lo));
    return r;
}
__device__ __forceinline__ void ldsm4(uint32_t* r, uint32_t addr) {
    asm volatile("ldmatrix.sync.aligned.m8n8.x4.shared.b16 {%0,%1,%2,%3}, [%4];"
        : "=r"(r[0]), "=r"(r[1]), "=r"(r[2]), "=r"(r[3]) : "r"(addr));
}
__device__ __forceinline__ void mma16816(float* d, const uint32_t* a, const uint32_t* b) {
    asm volatile("mma.sync.aligned.m16n8k16.row.col.f32.f16.f16.f32 "
        "{%0,%1,%2,%3}, {%4,%5,%6,%7}, {%8,%9}, {%0,%1,%2,%3};"
        : "+f"(d[0]), "+f"(d[1]), "+f"(d[2]), "+f"(d[3])
        : "r"(a[0]), "r"(a[1]), "r"(a[2]), "r"(a[3]), "r"(b[0]), "r"(b[1]));
}

// =====================================================================
// Kernel 1: Wh = h @ W^T ; also emits g_WhT (fp16, [f][j])
// =====================================================================
__global__ __launch_bounds__(256) void k_wh(const float* __restrict__ h,
                                            const float* __restrict__ W) {
    __shared__ __align__(16) float sh_h[64][68];
    __shared__ __align__(16) float sh_w[64][FOUT + 4];
    const int tid = threadIdx.x;
    const int i0  = blockIdx.x * 64;
    const int fg  = tid & 15;
    const int rg  = tid >> 4;

    float acc[4][8];
#pragma unroll
    for (int r = 0; r < 4; r++)
#pragma unroll
        for (int u = 0; u < 8; u++) acc[r][u] = 0.f;

    for (int kt = 0; kt < FIN / 64; kt++) {
        const int c0 = kt * 64;
        __syncthreads();
        {
            const int rr = tid >> 2, cc0 = (tid & 3) * 16;
#pragma unroll
            for (int u = 0; u < 4; u++)
                *(float4*)&sh_h[rr][cc0 + 4 * u] =
                    *(const float4*)&h[(size_t)(i0 + rr) * FIN + c0 + cc0 + 4 * u];
        }
        {
            const int f = tid >> 1, cc0 = (tid & 1) * 32;
#pragma unroll
            for (int u = 0; u < 8; u++) {
                float4 v = *(const float4*)&W[(size_t)f * FIN + c0 + cc0 + 4 * u];
                sh_w[cc0 + 4 * u + 0][f] = v.x;
                sh_w[cc0 + 4 * u + 1][f] = v.y;
                sh_w[cc0 + 4 * u + 2][f] = v.z;
                sh_w[cc0 + 4 * u + 3][f] = v.w;
            }
        }
        __syncthreads();
#pragma unroll 4
        for (int c = 0; c < 64; c++) {
            float hv[4];
#pragma unroll
            for (int r = 0; r < 4; r++) hv[r] = sh_h[rg * 4 + r][c];
            float4 wa = *(const float4*)&sh_w[c][fg * 8];
            float4 wb = *(const float4*)&sh_w[c][fg * 8 + 4];
#pragma unroll
            for (int r = 0; r < 4; r++) {
                acc[r][0] += hv[r] * wa.x;  acc[r][1] += hv[r] * wa.y;
                acc[r][2] += hv[r] * wa.z;  acc[r][3] += hv[r] * wa.w;
                acc[r][4] += hv[r] * wb.x;  acc[r][5] += hv[r] * wb.y;
                acc[r][6] += hv[r] * wb.z;  acc[r][7] += hv[r] * wb.w;
            }
        }
    }
#pragma unroll
    for (int r = 0; r < 4; r++) {
        const int row = i0 + rg * 4 + r;
        float4 oa = {acc[r][0], acc[r][1], acc[r][2], acc[r][3]};
        float4 ob = {acc[r][4], acc[r][5], acc[r][6], acc[r][7]};
        *(float4*)&g_Wh[(size_t)row * FOUT + fg * 8]     = oa;
        *(float4*)&g_Wh[(size_t)row * FOUT + fg * 8 + 4] = ob;
    }
    // ---- stage fp16 transpose through smem (alias sh_h: 16KB <= 17.4KB) ----
    __syncthreads();
    __half* sht = (__half*)sh_h;   // [f(128)][row_local(64)]
#pragma unroll
    for (int r = 0; r < 4; r++)
#pragma unroll
        for (int u = 0; u < 8; u++)
            sht[(fg * 8 + u) * 64 + rg * 4 + r] = __float2half_rn(acc[r][u]);
    __syncthreads();
    {
        const int f = tid >> 1, half_ = tid & 1;
        const uint4* src = (const uint4*)(sht + f * 64 + half_ * 32);
        uint4* dst = (uint4*)(g_WhT + (size_t)f * N + i0 + half_ * 32);
#pragma unroll
        for (int u = 0; u < 4; u++) dst[u] = src[u];
    }
}

// =====================================================================
// Kernel 2: per-row attention scalars
// =====================================================================
__global__ __launch_bounds__(256) void k_s(const float* __restrict__ a) {
    const int row  = blockIdx.x * 8 + (threadIdx.x >> 5);
    const int lane = threadIdx.x & 31;
    float ssrc = 0.f, sdst = 0.f;
#pragma unroll
    for (int u = 0; u < 4; u++) {
        const int f = lane + u * 32;
        float v = g_Wh[(size_t)row * FOUT + f];
        ssrc += v * a[f];
        sdst += v * a[FOUT + f];
    }
#pragma unroll
    for (int o = 16; o; o >>= 1) {
        ssrc += __shfl_xor_sync(0xffffffffu, ssrc, o);
        sdst += __shfl_xor_sync(0xffffffffu, sdst, o);
    }
    if (lane == 0) {
        g_p[row]  = expf(ssrc);
        g_r[row]  = expf(0.2f * ssrc);
        g_th[row] = -ssrc;
        g_q[row]  = expf(sdst);
        g_t[row]  = expf(0.2f * sdst);
        g_sd[row] = sdst;
    }
}

// =====================================================================
// Kernel 3: attention GEMM via mma.sync fp16 (m16n8k16), split-K x2.
// grid 128: bx>>1 = M-tile (128 rows), bx&1 = K half. 256 threads.
// =====================================================================
#define ASTRIDE 72   // fp16 elements per row (144 B) -> conflict-free ldmatrix

__global__ __launch_bounds__(256) void k_att(const int* __restrict__ adj) {
    __shared__ __align__(16) __half Ash[128][ASTRIDE];
    __shared__ __align__(16) __half Bsh[128][ASTRIDE];
    __shared__ float psh[128], rsh[128], thsh[128];

    const int tid  = threadIdx.x;
    const int lane = tid & 31;
    const int wid  = tid >> 5;
    const int bx   = blockIdx.x;
    const int i0   = (bx >> 1) * 128;
    const int jb   = (bx & 1) * KHALF;

    if (tid < 128) {
        psh[tid]  = g_p[i0 + tid];
        rsh[tid]  = g_r[i0 + tid];
        thsh[tid] = g_th[i0 + tid];
    }

    char* Ab = (char*)&Ash[0][0];
    char* Bb = (char*)&Bsh[0][0];
    const uint32_t AshAddr = smem_u32(Ab);
    const uint32_t BshAddr = smem_u32(Bb);

    // warp tiling: mw = m-block (32 rows), nw = n-block (64 cols)
    const int mw = wid & 3, nw = wid >> 2;
    // ldmatrix lane address components
    const int arow = lane & 15, ak8 = (lane >> 4) * 8;                 // A 16x16
    const int brow = (lane & 7) + ((lane >> 4) << 3);                  // B two 8x8 n-blocks
    const int bk8  = ((lane >> 3) & 1) * 8;
    const uint32_t aAddr0 = AshAddr + (uint32_t)(mw * 32 + arow) * 144 + ak8 * 2;
    const uint32_t bAddr0 = BshAddr + (uint32_t)(nw * 64 + brow) * 144 + bk8 * 2;

    float acc[2][8][4];
#pragma unroll
    for (int mt = 0; mt < 2; mt++)
#pragma unroll
        for (int nt = 0; nt < 8; nt++)
#pragma unroll
            for (int u = 0; u < 4; u++) acc[mt][nt][u] = 0.f;
    float dacc[16];
#pragma unroll
    for (int u = 0; u < 16; u++) dacc[u] = 0.f;

    const int bf = tid >> 1, bhalf = tid & 1;   // B-load assignment

    // ---- prefetch chunk 0 ----
    int2   aj[16];
    float2 q2, t2, s2;
    uint4  breg[4];
    {
        const int j0 = jb;
        q2 = *(const float2*)&g_q[j0 + 2 * lane];
        t2 = *(const float2*)&g_t[j0 + 2 * lane];
        s2 = *(const float2*)&g_sd[j0 + 2 * lane];
#pragma unroll
        for (int rr = 0; rr < 16; rr++)
            aj[rr] = *(const int2*)&adj[(size_t)(i0 + wid * 16 + rr) * N + j0 + 2 * lane];
        const uint4* src = (const uint4*)(g_WhT + (size_t)bf * N + j0 + bhalf * 32);
#pragma unroll
        for (int u = 0; u < 4; u++) breg[u] = src[u];
    }
    __syncthreads();

    for (int t = 0; t < NT; t++) {
        // ---- stage: B regs -> smem ----
#pragma unroll
        for (int u = 0; u < 4; u++)
            *(uint4*)(Bb + bf * 144 + bhalf * 64 + u * 16) = breg[u];
        // ---- stage: weights -> Ash, denominator accumulate ----
#pragma unroll
        for (int rr = 0; rr < 16; rr++) {
            const int row = wid * 16 + rr;
            const float pv = psh[row], rv = rsh[row], th = thsh[row];
            float w0 = 0.f, w1 = 0.f;
            if (aj[rr].x > 0) w0 = (s2.x > th) ? pv * q2.x : rv * t2.x;
            if (aj[rr].y > 0) w1 = (s2.y > th) ? pv * q2.y : rv * t2.y;
            *(uint32_t*)(Ab + row * 144 + lane * 4) = pack_f16x2(w0, w1);
            dacc[rr] += w0 + w1;
        }
        // ---- prefetch next chunk (latency hidden under mma phase) ----
        {
            const int jn = (t + 1 < NT) ? jb + (t + 1) * KC : jb;
            q2 = *(const float2*)&g_q[jn + 2 * lane];
            t2 = *(const float2*)&g_t[jn + 2 * lane];
            s2 = *(const float2*)&g_sd[jn + 2 * lane];
#pragma unroll
            for (int rr = 0; rr < 16; rr++)
                aj[rr] = *(const int2*)&adj[(size_t)(i0 + wid * 16 + rr) * N + jn + 2 * lane];
            const uint4* src = (const uint4*)(g_WhT + (size_t)bf * N + jn + bhalf * 32);
#pragma unroll
            for (int u = 0; u < 4; u++) breg[u] = src[u];
        }
        __syncthreads();
        // ---- mma phase: 4 k-steps of 16 ----
#pragma unroll
        for (int ks = 0; ks < 4; ks++) {
            uint32_t af[2][4];
            ldsm4(af[0], aAddr0 + ks * 32);
            ldsm4(af[1], aAddr0 + 16 * 144 + ks * 32);
#pragma unroll
            for (int p = 0; p < 4; p++) {
                uint32_t bfr[4];
                ldsm4(bfr, bAddr0 + p * 16 * 144 + ks * 32);
                mma16816(acc[0][2 * p],     af[0], bfr);
                mma16816(acc[0][2 * p + 1], af[0], bfr + 2);
                mma16816(acc[1][2 * p],     af[1], bfr);
                mma16816(acc[1][2 * p + 1], af[1], bfr + 2);
            }
        }
        __syncthreads();
    }

    // ---- denominator partials ----
#pragma unroll
    for (int rr = 0; rr < 16; rr++) {
        float d = dacc[rr];
#pragma unroll
        for (int o = 16; o; o >>= 1) d += __shfl_xor_sync(0xffffffffu, d, o);
        if (lane == 0) g_pden[bx * 128 + wid * 16 + rr] = d;
    }

    // ---- epilogue: accumulators -> g_pD[bx][row][col] ----
    {
        const int gid = lane >> 2, tig = lane & 3;
        float* base = g_pD + (size_t)bx * 16384;
#pragma unroll
        for (int mt = 0; mt < 2; mt++) {
            const int row = mw * 32 + mt * 16 + gid;
#pragma unroll
            for (int nt = 0; nt < 8; nt++) {
                const int col = nw * 64 + nt * 8 + 2 * tig;
                float2 lo = {acc[mt][nt][0], acc[mt][nt][1]};
                float2 hi = {acc[mt][nt][2], acc[mt][nt][3]};
                *(float2*)(base + (size_t)row * 128 + col)       = lo;
                *(float2*)(base + (size_t)(row + 8) * 128 + col) = hi;
            }
        }
    }
}

// =====================================================================
// Kernel 4: combine split-K partials, normalize
// =====================================================================
__global__ __launch_bounds__(256) void k_red(float* __restrict__ out) {
    __shared__ float dinv[128];
    const int mt = blockIdx.x, tid = threadIdx.x;
    if (tid < 128)
        dinv[tid] = 1.0f / (g_pden[(2 * mt) * 128 + tid] + g_pden[(2 * mt + 1) * 128 + tid]);
    __syncthreads();
    const float4* p0 = (const float4*)(g_pD + (size_t)(2 * mt) * 16384);
    const float4* p1 = (const float4*)(g_pD + (size_t)(2 * mt + 1) * 16384);
    float4* o = (float4*)(out + (size_t)mt * 16384);
#pragma unroll
    for (int u = 0; u < 16; u++) {
        const int idx = tid + 256 * u;           // float4 index (4096 total)
        float4 a = p0[idx], b = p1[idx];
        const float inv = dinv[idx >> 5];        // row = (idx*4)>>7
        float4 r = {(a.x + b.x) * inv, (a.y + b.y) * inv,
                    (a.z + b.z) * inv, (a.w + b.w) * inv};
        o[idx] = r;
    }
}

extern "C" void kernel_launch(void* const* d_in, const int* in_sizes, int n_in,
                              void* d_out, int out_size) {
    const float* h   = (const float*)d_in[0];
    const int*   adj = (const int*)d_in[1];
    const float* W   = (const float*)d_in[2];
    const float* a   = (const float*)d_in[3];
    float* out = (float*)d_out;

    k_wh<<<N / 64, 256>>>(h, W);
    k_s<<<N / 8, 256>>>(a);
    k_att<<<64 * KSPLIT, 256>>>(adj);
    k_red<<<64, 256>>>(out);
}